// round 5
// baseline (speedup 1.0000x reference)
#include <cuda_runtime.h>
#include <cuda_bf16.h>
#include <float.h>

#define N_BINS 15
#define NUM_CLS 1000
#define NUM_SEG (NUM_CLS * N_BINS)

// Scratch: per-(class,bin) signed accumulation of (conf - acc).
// Zero-initialized at module load; the reduce kernel re-zeroes it after
// consuming it, so every graph replay starts from zeros.
__device__ float g_seg[NUM_SEG];
__device__ int g_lab64;  // 1 if labels buffer is int64, 0 if int32

// One-warp probe: if labels are int64 with values in [0,1000), every high
// 32-bit word is 0. If int32, the probed "high words" are other labels:
// all-zero across 128 samples has prob ~(1/1000)^128.
__global__ void probe_kernel(const int* __restrict__ labels32, int nprobe) {
    int lane = threadIdx.x;
    int nz = 0;
    for (int i = lane; i < nprobe; i += 32)
        nz |= labels32[2 * i + 1];
    unsigned any = __ballot_sync(0xFFFFFFFFu, nz != 0);
    if (lane == 0) g_lab64 = (any == 0) ? 1 : 0;
}

// One warp per row. Front-batched streaming loads (MLP=8/lane).
// Max first (pure FMNMX, no index), warp-reduce max, then exp-sum vs the
// GLOBAL warp max + argmax via exact-equality min-index. Merge is a plain
// sum + min — no rescale exps, no predicated index chains.
__global__ __launch_bounds__(256)
void ecce_main_kernel(const float* __restrict__ logits,
                      const void* __restrict__ labels,
                      int N, int C) {
    int warp = (blockIdx.x * blockDim.x + threadIdx.x) >> 5;
    int lane = threadIdx.x & 31;
    if (warp >= N) return;

    const float4* row = reinterpret_cast<const float4*>(logits + (size_t)warp * C);
    const int nvec = C >> 2;

    float s = 0.0f;
    int   idx = 0x7FFFFFFF;
    float M;

    if (nvec == 250) {
        // ---- specialized C=1000 path ----
        const float4 pad = make_float4(-FLT_MAX, -FLT_MAX, -FLT_MAX, -FLT_MAX);
        float4 v[8];
        #pragma unroll
        for (int k = 0; k < 8; k++) {
            int i = lane + (k << 5);
            v[k] = (i < 250) ? __ldcs(&row[i]) : pad;
        }
        // Phase A: local max, no index tracking (FMNMX tree).
        float m = -FLT_MAX;
        #pragma unroll
        for (int k = 0; k < 8; k++) {
            m = fmaxf(m, fmaxf(fmaxf(v[k].x, v[k].y), fmaxf(v[k].z, v[k].w)));
        }
        // Warp-reduce the max.
        #pragma unroll
        for (int off = 16; off > 0; off >>= 1)
            m = fmaxf(m, __shfl_xor_sync(0xFFFFFFFFu, m, off));
        M = m;
        // Phase B: exp-sum vs global max; argmax = min index where x == M.
        #pragma unroll
        for (int k = 0; k < 8; k++) {
            int base = (lane + (k << 5)) << 2;
            #pragma unroll
            for (int e = 0; e < 4; e++) {
                float x = (e == 0) ? v[k].x : (e == 1) ? v[k].y : (e == 2) ? v[k].z : v[k].w;
                s += __expf(x - M);
                if (x == M) idx = min(idx, base + e);
            }
        }
    } else {
        // ---- generic fallback: two passes over the row ----
        float m = -FLT_MAX;
        for (int i = lane; i < nvec; i += 32) {
            float4 v = __ldcs(&row[i]);
            m = fmaxf(m, fmaxf(fmaxf(v.x, v.y), fmaxf(v.z, v.w)));
        }
        #pragma unroll
        for (int off = 16; off > 0; off >>= 1)
            m = fmaxf(m, __shfl_xor_sync(0xFFFFFFFFu, m, off));
        M = m;
        for (int i = lane; i < nvec; i += 32) {
            float4 v = __ldcs(&row[i]);
            int base = i << 2;
            #pragma unroll
            for (int e = 0; e < 4; e++) {
                float x = (e == 0) ? v.x : (e == 1) ? v.y : (e == 2) ? v.z : v.w;
                s += __expf(x - M);
                if (x == M) idx = min(idx, base + e);
            }
        }
    }

    // Warp merge: plain sum + min-index.
    #pragma unroll
    for (int off = 16; off > 0; off >>= 1) {
        s   += __shfl_xor_sync(0xFFFFFFFFu, s, off);
        idx  = min(idx, __shfl_xor_sync(0xFFFFFFFFu, idx, off));
    }

    if (lane == 0) {
        float conf = 1.0f / s;  // = exp(M-M)/sum(exp(l - M))
        int bin = (int)ceilf(conf * (float)N_BINS) - 1;
        bin = min(max(bin, 0), N_BINS - 1);
        int lab;
        if (g_lab64) lab = (int)((const long long*)labels)[warp];
        else         lab = ((const int*)labels)[warp];
        lab = min(max(lab, 0), NUM_CLS - 1);  // defensive
        float acc = (idx == lab) ? 1.0f : 0.0f;
        atomicAdd(&g_seg[lab * N_BINS + bin], conf - acc);
    }
}

// Single-block reduction: ecce = sum(|seg|) / N, and re-zero g_seg.
__global__ __launch_bounds__(512)
void ecce_reduce_kernel(float* __restrict__ out, int N) {
    __shared__ float sh[512];
    float acc = 0.0f;
    for (int i = threadIdx.x; i < NUM_SEG; i += 512) {
        acc += fabsf(g_seg[i]);
        g_seg[i] = 0.0f;  // restore zero invariant for next replay
    }
    sh[threadIdx.x] = acc;
    __syncthreads();
    for (int off = 256; off > 0; off >>= 1) {
        if (threadIdx.x < off) sh[threadIdx.x] += sh[threadIdx.x + off];
        __syncthreads();
    }
    if (threadIdx.x == 0) out[0] = sh[0] / (float)N;
}

extern "C" void kernel_launch(void* const* d_in, const int* in_sizes, int n_in,
                              void* d_out, int out_size) {
    // Logits is the (much) larger input; don't assume ordering.
    int i_logits = (in_sizes[0] >= in_sizes[1]) ? 0 : 1;
    int i_labels = 1 - i_logits;

    const float* logits = (const float*)d_in[i_logits];
    const void*  labels = d_in[i_labels];
    float*       out    = (float*)d_out;

    int N = in_sizes[i_labels];           // 131072
    int C = in_sizes[i_logits] / N;       // 1000

    // Probe 128 entries: reads 1 KB of a >=512 KB buffer — safe either way.
    int nprobe = (N >= 256) ? 128 : (N / 2);
    probe_kernel<<<1, 32>>>((const int*)labels, nprobe);

    int warps_per_block = 256 / 32;       // 8 rows per block
    int blocks = (N + warps_per_block - 1) / warps_per_block;
    ecce_main_kernel<<<blocks, 256>>>(logits, labels, N, C);

    ecce_reduce_kernel<<<1, 512>>>(out, N);
}

// round 6
// speedup vs baseline: 1.0680x; 1.0680x over previous
#include <cuda_runtime.h>
#include <cuda_bf16.h>
#include <float.h>

#define N_BINS 15
#define NUM_CLS 1000
#define NUM_SEG (NUM_CLS * N_BINS)

// Scratch: per-(class,bin) signed accumulation of (conf - acc).
// Zero-initialized at module load; the reduce kernel re-zeroes it after
// consuming it, so every graph replay starts from zeros.
__device__ float g_seg[NUM_SEG];

// One warp per row (R3 main loop — measured ~84us, at bandwidth ceiling).
// Dtype probe is inlined: every warp ballots on the high 32-bit words of the
// first 32 would-be int64 labels (one hot L2 line shared grid-wide). If labels
// are int64 with values in [0,1000), all high words are 0; if int32, those
// words are other labels — all-zero has prob (1/1000)^32.
__global__ __launch_bounds__(256)
void ecce_main_kernel(const float* __restrict__ logits,
                      const void* __restrict__ labels,
                      int N, int C) {
    int warp = (blockIdx.x * blockDim.x + threadIdx.x) >> 5;
    int lane = threadIdx.x & 31;
    if (warp >= N) return;

    // ---- inline dtype probe (all warps agree; reads a single hot line) ----
    int nprobe = min(32, N >> 1);
    int nz = 0;
    if (lane < nprobe) nz = ((const int*)labels)[2 * lane + 1];
    unsigned any = __ballot_sync(0xFFFFFFFFu, nz != 0);
    bool lab64 = (any == 0);

    const float4* row = reinterpret_cast<const float4*>(logits + (size_t)warp * C);
    const int nvec = C >> 2;

    float m = -FLT_MAX;
    float s = 0.0f;
    int   idx = 0x7FFFFFFF;

    if (nvec == 250) {
        // ---- specialized C=1000 path: front-batch 8x LDG.128 per lane ----
        const float4 pad = make_float4(-FLT_MAX, -FLT_MAX, -FLT_MAX, -FLT_MAX);
        float4 v[8];
        #pragma unroll
        for (int k = 0; k < 8; k++) {
            int i = lane + (k << 5);
            v[k] = (i < 250) ? row[i] : pad;
        }
        // Phase A: local max + argmax (first occurrence; per-lane indices increase).
        #pragma unroll
        for (int k = 0; k < 8; k++) {
            int base = (lane + (k << 5)) << 2;
            #pragma unroll
            for (int e = 0; e < 4; e++) {
                float x = (e == 0) ? v[k].x : (e == 1) ? v[k].y : (e == 2) ? v[k].z : v[k].w;
                if (x > m) { m = x; idx = base + e; }
            }
        }
        // Phase B: un-rescaled exp-sum vs the lane-local max (pads give exp(-inf)=0).
        #pragma unroll
        for (int k = 0; k < 8; k++) {
            s += __expf(v[k].x - m) + __expf(v[k].y - m)
               + __expf(v[k].z - m) + __expf(v[k].w - m);
        }
    } else {
        // ---- generic fallback (online softmax) ----
        for (int i = lane; i < nvec; i += 32) {
            float4 v = row[i];
            int base = i << 2;
            #pragma unroll
            for (int e = 0; e < 4; e++) {
                float x = (e == 0) ? v.x : (e == 1) ? v.y : (e == 2) ? v.z : v.w;
                int j = base + e;
                if (x > m) {
                    s = s * __expf(m - x) + 1.0f;
                    m = x; idx = j;
                } else {
                    s += __expf(x - m);
                }
            }
        }
    }

    // Warp merge of (m, idx, s); tie-break toward lower index (first argmax).
    #pragma unroll
    for (int off = 16; off > 0; off >>= 1) {
        float m2 = __shfl_down_sync(0xFFFFFFFFu, m, off);
        float s2 = __shfl_down_sync(0xFFFFFFFFu, s, off);
        int   i2 = __shfl_down_sync(0xFFFFFFFFu, idx, off);
        if (m2 > m || (m2 == m && i2 < idx)) {
            s = s * __expf(m - m2) + s2;
            m = m2; idx = i2;
        } else {
            s += s2 * __expf(m2 - m);
        }
    }

    if (lane == 0) {
        float conf = 1.0f / s;  // = exp(0)/sum(exp(l - max))
        int bin = (int)ceilf(conf * (float)N_BINS) - 1;
        bin = min(max(bin, 0), N_BINS - 1);
        int lab;
        if (lab64) lab = (int)((const long long*)labels)[warp];
        else       lab = ((const int*)labels)[warp];
        lab = min(max(lab, 0), NUM_CLS - 1);  // defensive
        float acc = (idx == lab) ? 1.0f : 0.0f;
        atomicAdd(&g_seg[lab * N_BINS + bin], conf - acc);
    }
}

// Single-block reduction: ecce = sum(|seg|) / N, and re-zero g_seg for the
// next graph replay.
__global__ __launch_bounds__(512)
void ecce_reduce_kernel(float* __restrict__ out, int N) {
    __shared__ float sh[512];
    float acc = 0.0f;
    for (int i = threadIdx.x; i < NUM_SEG; i += 512) {
        acc += fabsf(g_seg[i]);
        g_seg[i] = 0.0f;  // restore zero invariant
    }
    sh[threadIdx.x] = acc;
    __syncthreads();
    for (int off = 256; off > 0; off >>= 1) {
        if (threadIdx.x < off) sh[threadIdx.x] += sh[threadIdx.x + off];
        __syncthreads();
    }
    if (threadIdx.x == 0) out[0] = sh[0] / (float)N;
}

extern "C" void kernel_launch(void* const* d_in, const int* in_sizes, int n_in,
                              void* d_out, int out_size) {
    // Logits is the (much) larger input; don't assume ordering.
    int i_logits = (in_sizes[0] >= in_sizes[1]) ? 0 : 1;
    int i_labels = 1 - i_logits;

    const float* logits = (const float*)d_in[i_logits];
    const void*  labels = d_in[i_labels];
    float*       out    = (float*)d_out;

    int N = in_sizes[i_labels];           // 131072
    int C = in_sizes[i_logits] / N;       // 1000

    int warps_per_block = 256 / 32;       // 8 rows per block
    int blocks = (N + warps_per_block - 1) / warps_per_block;
    ecce_main_kernel<<<blocks, 256>>>(logits, labels, N, C);

    ecce_reduce_kernel<<<1, 512>>>(out, N);
}

// round 7
// speedup vs baseline: 1.0932x; 1.0237x over previous
#include <cuda_runtime.h>
#include <cuda_bf16.h>
#include <float.h>

#define N_BINS 15
#define NUM_CLS 1000
#define NUM_SEG (NUM_CLS * N_BINS)   // 15000, divisible by 4

// Scratch: per-(class,bin) signed accumulation of (conf - acc).
// Zero-initialized at module load; the reduce kernel re-zeroes it after
// consuming it, so every graph replay starts from zeros.
__device__ float g_seg[NUM_SEG];

// One warp per row (R3 main loop — measured ~82us, at bandwidth ceiling).
// Dtype probe is inlined: every warp ballots on the high 32-bit words of the
// first 32 would-be int64 labels (one hot L2 line shared grid-wide). If labels
// are int64 with values in [0,1000), all high words are 0; if int32, those
// words are other labels — all-zero has prob (1/1000)^32.
__global__ __launch_bounds__(256)
void ecce_main_kernel(const float* __restrict__ logits,
                      const void* __restrict__ labels,
                      int N, int C) {
    int warp = (blockIdx.x * blockDim.x + threadIdx.x) >> 5;
    int lane = threadIdx.x & 31;
    if (warp >= N) return;

    // ---- inline dtype probe (all warps agree; reads a single hot line) ----
    int nprobe = min(32, N >> 1);
    int nz = 0;
    if (lane < nprobe) nz = ((const int*)labels)[2 * lane + 1];
    unsigned any = __ballot_sync(0xFFFFFFFFu, nz != 0);
    bool lab64 = (any == 0);

    const float4* row = reinterpret_cast<const float4*>(logits + (size_t)warp * C);
    const int nvec = C >> 2;

    float m = -FLT_MAX;
    float s = 0.0f;
    int   idx = 0x7FFFFFFF;

    if (nvec == 250) {
        // ---- specialized C=1000 path: front-batch 8x LDG.128 per lane ----
        const float4 pad = make_float4(-FLT_MAX, -FLT_MAX, -FLT_MAX, -FLT_MAX);
        float4 v[8];
        #pragma unroll
        for (int k = 0; k < 8; k++) {
            int i = lane + (k << 5);
            v[k] = (i < 250) ? row[i] : pad;
        }
        // Phase A: local max + argmax (first occurrence; per-lane indices increase).
        #pragma unroll
        for (int k = 0; k < 8; k++) {
            int base = (lane + (k << 5)) << 2;
            #pragma unroll
            for (int e = 0; e < 4; e++) {
                float x = (e == 0) ? v[k].x : (e == 1) ? v[k].y : (e == 2) ? v[k].z : v[k].w;
                if (x > m) { m = x; idx = base + e; }
            }
        }
        // Phase B: un-rescaled exp-sum vs the lane-local max (pads give exp(-inf)=0).
        #pragma unroll
        for (int k = 0; k < 8; k++) {
            s += __expf(v[k].x - m) + __expf(v[k].y - m)
               + __expf(v[k].z - m) + __expf(v[k].w - m);
        }
    } else {
        // ---- generic fallback (online softmax) ----
        for (int i = lane; i < nvec; i += 32) {
            float4 v = row[i];
            int base = i << 2;
            #pragma unroll
            for (int e = 0; e < 4; e++) {
                float x = (e == 0) ? v.x : (e == 1) ? v.y : (e == 2) ? v.z : v.w;
                int j = base + e;
                if (x > m) {
                    s = s * __expf(m - x) + 1.0f;
                    m = x; idx = j;
                } else {
                    s += __expf(x - m);
                }
            }
        }
    }

    // Warp merge of (m, idx, s); tie-break toward lower index (first argmax).
    #pragma unroll
    for (int off = 16; off > 0; off >>= 1) {
        float m2 = __shfl_down_sync(0xFFFFFFFFu, m, off);
        float s2 = __shfl_down_sync(0xFFFFFFFFu, s, off);
        int   i2 = __shfl_down_sync(0xFFFFFFFFu, idx, off);
        if (m2 > m || (m2 == m && i2 < idx)) {
            s = s * __expf(m - m2) + s2;
            m = m2; idx = i2;
        } else {
            s += s2 * __expf(m2 - m);
        }
    }

    if (lane == 0) {
        float conf = 1.0f / s;  // = exp(0)/sum(exp(l - max))
        int bin = (int)ceilf(conf * (float)N_BINS) - 1;
        bin = min(max(bin, 0), N_BINS - 1);
        int lab;
        if (lab64) lab = (int)((const long long*)labels)[warp];
        else       lab = ((const int*)labels)[warp];
        lab = min(max(lab, 0), NUM_CLS - 1);  // defensive
        float acc = (idx == lab) ? 1.0f : 0.0f;
        atomicAdd(&g_seg[lab * N_BINS + bin], conf - acc);
    }
}

// Single-block reduction: ecce = sum(|seg|) / N, and re-zero g_seg for the
// next graph replay. float4 loads/stores, 1024 threads: ~4 independent
// LDG.128 per thread -> latency exposed once, not 30x.
__global__ __launch_bounds__(1024)
void ecce_reduce_kernel(float* __restrict__ out, int N) {
    __shared__ float sh[32];
    float4* p = reinterpret_cast<float4*>(g_seg);
    const float4 zero4 = make_float4(0.f, 0.f, 0.f, 0.f);

    float acc = 0.0f;
    #pragma unroll 4
    for (int i = threadIdx.x; i < NUM_SEG / 4; i += 1024) {
        float4 v = p[i];
        acc += fabsf(v.x) + fabsf(v.y) + fabsf(v.z) + fabsf(v.w);
        p[i] = zero4;  // restore zero invariant
    }

    // Warp reduce, then cross-warp via shared.
    #pragma unroll
    for (int off = 16; off > 0; off >>= 1)
        acc += __shfl_xor_sync(0xFFFFFFFFu, acc, off);
    int wid = threadIdx.x >> 5, lane = threadIdx.x & 31;
    if (lane == 0) sh[wid] = acc;
    __syncthreads();
    if (wid == 0) {
        acc = (lane < 32) ? sh[lane] : 0.0f;
        #pragma unroll
        for (int off = 16; off > 0; off >>= 1)
            acc += __shfl_xor_sync(0xFFFFFFFFu, acc, off);
        if (lane == 0) out[0] = acc / (float)N;
    }
}

extern "C" void kernel_launch(void* const* d_in, const int* in_sizes, int n_in,
                              void* d_out, int out_size) {
    // Logits is the (much) larger input; don't assume ordering.
    int i_logits = (in_sizes[0] >= in_sizes[1]) ? 0 : 1;
    int i_labels = 1 - i_logits;

    const float* logits = (const float*)d_in[i_logits];
    const void*  labels = d_in[i_labels];
    float*       out    = (float*)d_out;

    int N = in_sizes[i_labels];           // 131072
    int C = in_sizes[i_logits] / N;       // 1000

    int warps_per_block = 256 / 32;       // 8 rows per block
    int blocks = (N + warps_per_block - 1) / warps_per_block;
    ecce_main_kernel<<<blocks, 256>>>(logits, labels, N, C);

    ecce_reduce_kernel<<<1, 1024>>>(out, N);
}